// round 9
// baseline (speedup 1.0000x reference)
#include <cuda_runtime.h>
#include <cuda_bf16.h>
#include <cstdint>

#define NCTA 256
#define THR  256

// smem word offsets (4B words)
#define W_XH   0        // 64*36
#define W_XL   2304
#define W_DWH  4608     // 64*36
#define W_DWL  6912
#define W_UH   0        // 128*36 (reuses G1 staging region)
#define W_UL   4608
#define W_DSM  9216     // 64*66 f32
#define W_RH   13440    // 64*36
#define W_RL   15744
#define SMEM_SZ (18048*4)

// pre-split weights (bf16 hi/lo)
__device__ unsigned short g_dwh[64*4096], g_dwl[64*4096];
__device__ unsigned short g_uwh[4096*64], g_uwl[4096*64];

static __device__ __forceinline__ uint32_t pk2(float lo, float hi) {
    uint32_t r; asm("cvt.rn.bf16x2.f32 %0, %1, %2;" : "=r"(r) : "f"(hi), "f"(lo)); return r;
}
static __device__ __forceinline__ void split4w(float4 v, uint32_t& h0, uint32_t& h1,
                                               uint32_t& l0, uint32_t& l1) {
    h0 = pk2(v.x, v.y); h1 = pk2(v.z, v.w);
    float ax = __uint_as_float(h0 << 16), ay = __uint_as_float(h0 & 0xffff0000u);
    float az = __uint_as_float(h1 << 16), aw = __uint_as_float(h1 & 0xffff0000u);
    l0 = pk2(v.x - ax, v.y - ay); l1 = pk2(v.z - az, v.w - aw);
}
static __device__ __forceinline__ void bmma(float d[4], const uint32_t a[4],
                                            uint32_t b0, uint32_t b1) {
    asm("mma.sync.aligned.m16n8k16.row.col.f32.bf16.bf16.f32 "
        "{%0,%1,%2,%3},{%4,%5,%6,%7},{%8,%9},{%0,%1,%2,%3};"
        : "+f"(d[0]), "+f"(d[1]), "+f"(d[2]), "+f"(d[3])
        : "r"(a[0]), "r"(a[1]), "r"(a[2]), "r"(a[3]), "r"(b0), "r"(b1));
}

__global__ void kprep(const float* __restrict__ dw, const float* __restrict__ uw) {
    int i = blockIdx.x * 256 + threadIdx.x;
    float v = (i < 262144) ? dw[i] : uw[i - 262144];
    __nv_bfloat16 hb = __float2bfloat16(v);
    float l = v - __bfloat162float(hb);
    __nv_bfloat16 lb = __float2bfloat16(l);
    unsigned short hu = *(unsigned short*)&hb, lu = *(unsigned short*)&lb;
    if (i < 262144) { g_dwh[i] = hu; g_dwl[i] = lu; }
    else            { g_uwh[i - 262144] = hu; g_uwl[i - 262144] = lu; }
}

__global__ __launch_bounds__(THR, 2) void moe_mma(
    const float* __restrict__ x, const float* __restrict__ tv,
    const long long* __restrict__ ti, float* __restrict__ out)
{
    extern __shared__ uint32_t sm[];
    const int tid = threadIdx.x, wid = tid >> 5, lane = tid & 31;
    const int lr = lane >> 2, lc = lane & 3;
    const int mt = wid >> 1, nh = wid & 1;       // warp = m-tile mt (16 rows), n-half nh (32 cols)
    const int rm = mt * 16;
    const int row0 = blockIdx.x * 64;

    // ---- pack top-k indices (int32/int64 auto-detect, in-bounds) ----
    uint32_t plo = 0, phi = 0;
    {
        const int* t32b = (const int*)ti;
        bool is64 = ((t32b[1]|t32b[3]|t32b[5]|t32b[7]|t32b[9]|t32b[11]|t32b[13]|t32b[15]) == 0);
        if (tid < 64) {
            int row = row0 + tid;
            if (is64) {
                const long long* t = ti + (size_t)row * 8;
                #pragma unroll
                for (int k = 0; k < 4; k++) { plo |= ((uint32_t)t[k]&63u)<<(8*k); phi |= ((uint32_t)t[4+k]&63u)<<(8*k); }
            } else {
                const int* t = t32b + (size_t)row * 8;
                #pragma unroll
                for (int k = 0; k < 4; k++) { plo |= ((uint32_t)t[k]&63u)<<(8*k); phi |= ((uint32_t)t[4+k]&63u)<<(8*k); }
            }
        }
    }

    // ================== GEMM1: D1[64,64] = X_tile @ dw^T (bf16x3) ==================
    const float4* x4   = (const float4*)x;
    const uint4*  dwh4 = (const uint4*)g_dwh;
    const uint4*  dwl4 = (const uint4*)g_dwl;

    float acc[4][4];
    #pragma unroll
    for (int t = 0; t < 4; t++) { acc[t][0]=acc[t][1]=acc[t][2]=acc[t][3]=0.f; }

    float4 px[4]; uint4 pwh[2], pwl[2];
    #pragma unroll
    for (int j = 0; j < 4; j++) { int f = tid + j*256; px[j] = x4[(size_t)(row0 + (f>>4))*1024 + (f&15)]; }
    #pragma unroll
    for (int j = 0; j < 2; j++) { int f = tid + j*256; pwh[j] = dwh4[(f>>3)*512 + (f&7)]; pwl[j] = dwl4[(f>>3)*512 + (f&7)]; }

    #pragma unroll 1
    for (int c = 0; c < 64; c++) {
        __syncthreads();
        #pragma unroll
        for (int j = 0; j < 4; j++) {
            int f = tid + j*256, row = f>>4, q = f&15;
            uint32_t h0,h1,l0,l1; split4w(px[j], h0,h1,l0,l1);
            uint32_t wa = row*36 + q*2;
            *(uint2*)&sm[W_XH + wa] = make_uint2(h0,h1);
            *(uint2*)&sm[W_XL + wa] = make_uint2(l0,l1);
        }
        #pragma unroll
        for (int j = 0; j < 2; j++) {
            int f = tid + j*256, n = f>>3, qw = f&7;
            uint32_t wa = n*36 + qw*4;
            *(uint4*)&sm[W_DWH + wa] = pwh[j];
            *(uint4*)&sm[W_DWL + wa] = pwl[j];
        }
        __syncthreads();
        if (c < 63) {
            #pragma unroll
            for (int j = 0; j < 4; j++) { int f = tid + j*256; px[j] = x4[(size_t)(row0 + (f>>4))*1024 + (c+1)*16 + (f&15)]; }
            #pragma unroll
            for (int j = 0; j < 2; j++) { int f = tid + j*256; pwh[j] = dwh4[(f>>3)*512 + (c+1)*8 + (f&7)]; pwl[j] = dwl4[(f>>3)*512 + (c+1)*8 + (f&7)]; }
        }
        #pragma unroll
        for (int s = 0; s < 4; s++) {
            uint32_t ah[4], al[4];
            uint32_t wa = (rm + lr)*36 + s*8 + lc;
            ah[0] = sm[W_XH+wa]; ah[1] = sm[W_XH+wa+288]; ah[2] = sm[W_XH+wa+4]; ah[3] = sm[W_XH+wa+292];
            al[0] = sm[W_XL+wa]; al[1] = sm[W_XL+wa+288]; al[2] = sm[W_XL+wa+4]; al[3] = sm[W_XL+wa+292];
            #pragma unroll
            for (int t = 0; t < 4; t++) {
                uint32_t wb = ((nh*4 + t)*8 + lr)*36 + s*8 + lc;
                uint32_t bh0 = sm[W_DWH+wb], bh1 = sm[W_DWH+wb+4];
                uint32_t bl0 = sm[W_DWL+wb], bl1 = sm[W_DWL+wb+4];
                bmma(acc[t], ah, bh0, bh1);
                bmma(acc[t], ah, bl0, bl1);
                bmma(acc[t], al, bh0, bh1);
            }
        }
    }

    // ---- epilogue1: D1 frags -> Dsm, zero R ----
    __syncthreads();
    #pragma unroll
    for (int t = 0; t < 4; t++) {
        uint32_t wd = (rm + lr)*66 + (nh*4 + t)*8 + lc*2;
        *(float2*)&sm[W_DSM + wd]       = make_float2(acc[t][0], acc[t][1]);
        *(float2*)&sm[W_DSM + wd + 528] = make_float2(acc[t][2], acc[t][3]);   // +8 rows
    }
    #pragma unroll
    for (int j = 0; j < 18; j++) sm[W_RH + tid + j*256] = 0;    // Rh+Rl = 4608 words
    __syncthreads();

    // prefetch G2 chunk 0 while gathering
    const uint4* uwh4 = (const uint4*)g_uwh;
    const uint4* uwl4 = (const uint4*)g_uwl;
    uint4 pu[8];
    #pragma unroll
    for (int j = 0; j < 4; j++) {
        int f = tid + j*256, n = f>>3, qw = f&7;
        pu[j] = uwh4[n*8+qw]; pu[j+4] = uwl4[n*8+qw];
    }

    // ---- gather * scale -> sparse R (bf16 split) ----
    if (tid < 64) {
        const float* tvr = tv + (size_t)(row0 + tid)*8;
        #pragma unroll
        for (int k = 0; k < 8; k++) {
            uint32_t idx = ((k < 4 ? plo : phi) >> (8*(k&3))) & 63u;
            float v = ((float*)&sm[W_DSM])[tid*66 + idx] * tvr[k];
            __nv_bfloat16 hb = __float2bfloat16(v);
            float l = v - __bfloat162float(hb);
            __nv_bfloat16 lb = __float2bfloat16(l);
            ((unsigned short*)&sm[W_RH])[tid*72 + idx] = *(unsigned short*)&hb;
            ((unsigned short*)&sm[W_RL])[tid*72 + idx] = *(unsigned short*)&lb;
        }
    }
    __syncthreads();

    // ---- R fragments register-resident for all of GEMM2 ----
    uint32_t Ah[4][4], Al[4][4];
    #pragma unroll
    for (int s = 0; s < 4; s++) {
        uint32_t wa = (rm + lr)*36 + s*8 + lc;
        Ah[s][0] = sm[W_RH+wa]; Ah[s][1] = sm[W_RH+wa+288]; Ah[s][2] = sm[W_RH+wa+4]; Ah[s][3] = sm[W_RH+wa+292];
        Al[s][0] = sm[W_RL+wa]; Al[s][1] = sm[W_RL+wa+288]; Al[s][2] = sm[W_RL+wa+4]; Al[s][3] = sm[W_RL+wa+292];
    }

    // ================== GEMM2: out[64,4096] = R[64,64] @ uw^T, 32 chunks of 128 cols ==========
    #pragma unroll 1
    for (int ch = 0; ch < 32; ch++) {
        __syncthreads();
        #pragma unroll
        for (int j = 0; j < 4; j++) {
            int f = tid + j*256, n = f>>3, qw = f&7;
            uint32_t wa = n*36 + qw*4;
            *(uint4*)&sm[W_UH + wa] = pu[j];
            *(uint4*)&sm[W_UL + wa] = pu[j+4];
        }
        __syncthreads();
        if (ch < 31) {
            #pragma unroll
            for (int j = 0; j < 4; j++) {
                int f = tid + j*256, n = f>>3, qw = f&7;
                pu[j]   = uwh4[((ch+1)*128 + n)*8 + qw];
                pu[j+4] = uwl4[((ch+1)*128 + n)*8 + qw];
            }
        }
        #pragma unroll 2
        for (int tt = 0; tt < 8; tt++) {
            int t = nh*8 + tt;                 // this warp's n8-tile within chunk
            float d[4] = {0.f, 0.f, 0.f, 0.f};
            #pragma unroll
            for (int s = 0; s < 4; s++) {
                uint32_t wb = (t*8 + lr)*36 + s*8 + lc;
                uint32_t bh0 = sm[W_UH+wb], bh1 = sm[W_UH+wb+4];
                uint32_t bl0 = sm[W_UL+wb], bl1 = sm[W_UL+wb+4];
                bmma(d, Ah[s], bh0, bh1);
                bmma(d, Ah[s], bl0, bl1);
                bmma(d, Al[s], bh0, bh1);
            }
            size_t o = (size_t)(row0 + rm + lr)*4096 + ch*128 + t*8 + lc*2;
            *(float2*)&out[o]          = make_float2(d[0], d[1]);
            *(float2*)&out[o + 8*4096] = make_float2(d[2], d[3]);
        }
    }
}

extern "C" void kernel_launch(void* const* d_in, const int* in_sizes, int n_in,
                              void* d_out, int out_size)
{
    const float*     x  = (const float*)d_in[0];      // [16384,4096]
    const float*     dw = (const float*)d_in[1];      // [64,4096]
    const float*     uw = (const float*)d_in[2];      // [4096,64]
    const float*     tv = (const float*)d_in[3];      // [16384,8]
    const long long* ti = (const long long*)d_in[4];  // [16384,8] i32/i64

    cudaFuncSetAttribute(moe_mma, cudaFuncAttributeMaxDynamicSharedMemorySize, SMEM_SZ);
    kprep<<<2048, 256>>>(dw, uw);
    moe_mma<<<NCTA, THR, SMEM_SZ>>>(x, tv, ti, (float*)d_out);
}

// round 10
// speedup vs baseline: 1.0603x; 1.0603x over previous
#include <cuda_runtime.h>
#include <cuda_bf16.h>
#include <cstdint>

#define NCTA 128
#define THR  512

// smem word offsets (4B words)
#define W_XH   0        // 128*36
#define W_XL   4608
#define W_DWH  9216     // 64*36
#define W_DWL  11520
#define W_UH   0        // 128*36 (reuses G1 staging region)
#define W_UL   4608
#define W_DSM  13824    // 128*66 f32
#define W_RH   22272    // 128*36
#define W_RL   26880
#define SMEM_SZ (31488*4)

// pre-split weights (bf16 hi/lo)
__device__ unsigned short g_dwh[64*4096], g_dwl[64*4096];
__device__ unsigned short g_uwh[4096*64], g_uwl[4096*64];

static __device__ __forceinline__ uint32_t pk2(float lo, float hi) {
    uint32_t r; asm("cvt.rn.bf16x2.f32 %0, %1, %2;" : "=r"(r) : "f"(hi), "f"(lo)); return r;
}
static __device__ __forceinline__ void split4w(float4 v, uint32_t& h0, uint32_t& h1,
                                               uint32_t& l0, uint32_t& l1) {
    h0 = pk2(v.x, v.y); h1 = pk2(v.z, v.w);
    float ax = __uint_as_float(h0 << 16), ay = __uint_as_float(h0 & 0xffff0000u);
    float az = __uint_as_float(h1 << 16), aw = __uint_as_float(h1 & 0xffff0000u);
    l0 = pk2(v.x - ax, v.y - ay); l1 = pk2(v.z - az, v.w - aw);
}
static __device__ __forceinline__ void bmma(float d[4], const uint32_t a[4],
                                            uint32_t b0, uint32_t b1) {
    asm("mma.sync.aligned.m16n8k16.row.col.f32.bf16.bf16.f32 "
        "{%0,%1,%2,%3},{%4,%5,%6,%7},{%8,%9},{%0,%1,%2,%3};"
        : "+f"(d[0]), "+f"(d[1]), "+f"(d[2]), "+f"(d[3])
        : "r"(a[0]), "r"(a[1]), "r"(a[2]), "r"(a[3]), "r"(b0), "r"(b1));
}

__global__ void kprep(const float* __restrict__ dw, const float* __restrict__ uw) {
    int i = blockIdx.x * 256 + threadIdx.x;
    float v = (i < 262144) ? dw[i] : uw[i - 262144];
    __nv_bfloat16 hb = __float2bfloat16(v);
    float l = v - __bfloat162float(hb);
    __nv_bfloat16 lb = __float2bfloat16(l);
    unsigned short hu = *(unsigned short*)&hb, lu = *(unsigned short*)&lb;
    if (i < 262144) { g_dwh[i] = hu; g_dwl[i] = lu; }
    else            { g_uwh[i - 262144] = hu; g_uwl[i - 262144] = lu; }
}

__global__ __launch_bounds__(THR, 1) void moe_mma(
    const float* __restrict__ x, const float* __restrict__ tv,
    const long long* __restrict__ ti, float* __restrict__ out)
{
    extern __shared__ uint32_t sm[];
    const int tid = threadIdx.x, wid = tid >> 5, lane = tid & 31;
    const int lr = lane >> 2, lc = lane & 3;
    const int wm = wid >> 2, wn = wid & 3;       // 4 m-groups (m32) x 4 n-groups
    const int row0 = blockIdx.x * 128;

    // ---- pack top-k indices (int32/int64 auto-detect, in-bounds) ----
    uint32_t plo = 0, phi = 0;
    {
        const int* t32b = (const int*)ti;
        bool is64 = ((t32b[1]|t32b[3]|t32b[5]|t32b[7]|t32b[9]|t32b[11]|t32b[13]|t32b[15]) == 0);
        if (tid < 128) {
            int row = row0 + tid;
            if (is64) {
                const long long* t = ti + (size_t)row * 8;
                #pragma unroll
                for (int k = 0; k < 4; k++) { plo |= ((uint32_t)t[k]&63u)<<(8*k); phi |= ((uint32_t)t[4+k]&63u)<<(8*k); }
            } else {
                const int* t = t32b + (size_t)row * 8;
                #pragma unroll
                for (int k = 0; k < 4; k++) { plo |= ((uint32_t)t[k]&63u)<<(8*k); phi |= ((uint32_t)t[4+k]&63u)<<(8*k); }
            }
        }
    }

    // ================== GEMM1: D1[128,64] = X_tile @ dw^T (bf16x3) ==================
    // warp tile: m32 (m-tiles wm*2, wm*2+1) x n16 (n-tiles wn*2, wn*2+1)
    const float4* x4   = (const float4*)x;
    const uint4*  dwh4 = (const uint4*)g_dwh;
    const uint4*  dwl4 = (const uint4*)g_dwl;

    float acc[2][2][4];
    #pragma unroll
    for (int i = 0; i < 2; i++)
        #pragma unroll
        for (int t = 0; t < 2; t++) { acc[i][t][0]=acc[i][t][1]=acc[i][t][2]=acc[i][t][3]=0.f; }

    float4 px[4]; uint4 pwh, pwl;
    #pragma unroll
    for (int j = 0; j < 4; j++) { int f = tid + j*THR; px[j] = x4[(size_t)(row0 + (f>>4))*1024 + (f&15)]; }
    { int f = tid; pwh = dwh4[(f>>3)*512 + (f&7)]; pwl = dwl4[(f>>3)*512 + (f&7)]; }

    #pragma unroll 1
    for (int c = 0; c < 64; c++) {
        __syncthreads();
        #pragma unroll
        for (int j = 0; j < 4; j++) {
            int f = tid + j*THR, row = f>>4, q = f&15;
            uint32_t h0,h1,l0,l1; split4w(px[j], h0,h1,l0,l1);
            uint32_t wa = row*36 + q*2;
            *(uint2*)&sm[W_XH + wa] = make_uint2(h0,h1);
            *(uint2*)&sm[W_XL + wa] = make_uint2(l0,l1);
        }
        {
            int f = tid, n = f>>3, qw = f&7;
            uint32_t wa = n*36 + qw*4;
            *(uint4*)&sm[W_DWH + wa] = pwh;
            *(uint4*)&sm[W_DWL + wa] = pwl;
        }
        __syncthreads();
        if (c < 63) {
            #pragma unroll
            for (int j = 0; j < 4; j++) { int f = tid + j*THR; px[j] = x4[(size_t)(row0 + (f>>4))*1024 + (c+1)*16 + (f&15)]; }
            int f = tid; pwh = dwh4[(f>>3)*512 + (c+1)*8 + (f&7)]; pwl = dwl4[(f>>3)*512 + (c+1)*8 + (f&7)];
        }
        #pragma unroll
        for (int s = 0; s < 4; s++) {
            uint32_t ah[2][4], al[2][4];
            #pragma unroll
            for (int i = 0; i < 2; i++) {
                uint32_t wa = ((wm*2+i)*16 + lr)*36 + s*8 + lc;
                ah[i][0] = sm[W_XH+wa]; ah[i][1] = sm[W_XH+wa+288]; ah[i][2] = sm[W_XH+wa+4]; ah[i][3] = sm[W_XH+wa+292];
                al[i][0] = sm[W_XL+wa]; al[i][1] = sm[W_XL+wa+288]; al[i][2] = sm[W_XL+wa+4]; al[i][3] = sm[W_XL+wa+292];
            }
            #pragma unroll
            for (int t = 0; t < 2; t++) {
                uint32_t wb = ((wn*2+t)*8 + lr)*36 + s*8 + lc;
                uint32_t bh0 = sm[W_DWH+wb], bh1 = sm[W_DWH+wb+4];
                uint32_t bl0 = sm[W_DWL+wb], bl1 = sm[W_DWL+wb+4];
                #pragma unroll
                for (int i = 0; i < 2; i++) {
                    bmma(acc[i][t], ah[i], bh0, bh1);
                    bmma(acc[i][t], ah[i], bl0, bl1);
                    bmma(acc[i][t], al[i], bh0, bh1);
                }
            }
        }
    }

    // ---- epilogue1: D1 frags -> Dsm, zero R ----
    __syncthreads();
    #pragma unroll
    for (int i = 0; i < 2; i++)
        #pragma unroll
        for (int t = 0; t < 2; t++) {
            uint32_t wd = ((wm*2+i)*16 + lr)*66 + (wn*2+t)*8 + lc*2;
            *(float2*)&sm[W_DSM + wd]       = make_float2(acc[i][t][0], acc[i][t][1]);
            *(float2*)&sm[W_DSM + wd + 528] = make_float2(acc[i][t][2], acc[i][t][3]);   // +8 rows
        }
    #pragma unroll
    for (int j = 0; j < 9; j++) sm[W_RH + tid + j*THR] = 0;    // Rh+Rl = 9216 words
    __syncthreads();

    // prefetch G2 chunk 0 while gathering
    const uint4* uwh4 = (const uint4*)g_uwh;
    const uint4* uwl4 = (const uint4*)g_uwl;
    uint4 pu[4];
    #pragma unroll
    for (int j = 0; j < 2; j++) {
        int f = tid + j*THR, n = f>>3, qw = f&7;
        pu[j] = uwh4[n*8+qw]; pu[j+2] = uwl4[n*8+qw];
    }

    // ---- gather * scale -> sparse R (bf16 split) ----
    if (tid < 128) {
        const float* tvr = tv + (size_t)(row0 + tid)*8;
        #pragma unroll
        for (int k = 0; k < 8; k++) {
            uint32_t idx = ((k < 4 ? plo : phi) >> (8*(k&3))) & 63u;
            float v = ((float*)&sm[W_DSM])[tid*66 + idx] * tvr[k];
            __nv_bfloat16 hb = __float2bfloat16(v);
            float l = v - __bfloat162float(hb);
            __nv_bfloat16 lb = __float2bfloat16(l);
            ((unsigned short*)&sm[W_RH])[tid*72 + idx] = *(unsigned short*)&hb;
            ((unsigned short*)&sm[W_RL])[tid*72 + idx] = *(unsigned short*)&lb;
        }
    }
    __syncthreads();

    // ---- R fragments register-resident (2 m-tiles = m32 per warp) ----
    uint32_t Ah[2][4][4], Al[2][4][4];
    #pragma unroll
    for (int i = 0; i < 2; i++)
        #pragma unroll
        for (int s = 0; s < 4; s++) {
            uint32_t wa = ((wm*2+i)*16 + lr)*36 + s*8 + lc;
            Ah[i][s][0] = sm[W_RH+wa]; Ah[i][s][1] = sm[W_RH+wa+288]; Ah[i][s][2] = sm[W_RH+wa+4]; Ah[i][s][3] = sm[W_RH+wa+292];
            Al[i][s][0] = sm[W_RL+wa]; Al[i][s][1] = sm[W_RL+wa+288]; Al[i][s][2] = sm[W_RL+wa+4]; Al[i][s][3] = sm[W_RL+wa+292];
        }

    // ========== GEMM2: out[128,4096] = R @ uw^T, 32 chunks of 128 cols ==========
    // warp: m32 (its resident A) x n-quarter (4 of 16 n8-tiles per chunk)
    #pragma unroll 1
    for (int ch = 0; ch < 32; ch++) {
        __syncthreads();
        #pragma unroll
        for (int j = 0; j < 2; j++) {
            int f = tid + j*THR, n = f>>3, qw = f&7;
            uint32_t wa = n*36 + qw*4;
            *(uint4*)&sm[W_UH + wa] = pu[j];
            *(uint4*)&sm[W_UL + wa] = pu[j+2];
        }
        __syncthreads();
        if (ch < 31) {
            #pragma unroll
            for (int j = 0; j < 2; j++) {
                int f = tid + j*THR, n = f>>3, qw = f&7;
                pu[j]   = uwh4[((ch+1)*128 + n)*8 + qw];
                pu[j+2] = uwl4[((ch+1)*128 + n)*8 + qw];
            }
        }
        #pragma unroll
        for (int tt = 0; tt < 4; tt++) {
            int t = wn*4 + tt;                 // this warp's n8-tile within chunk
            float d0[4] = {0.f,0.f,0.f,0.f}, d1[4] = {0.f,0.f,0.f,0.f};
            #pragma unroll
            for (int s = 0; s < 4; s++) {
                uint32_t wb = (t*8 + lr)*36 + s*8 + lc;
                uint32_t bh0 = sm[W_UH+wb], bh1 = sm[W_UH+wb+4];
                uint32_t bl0 = sm[W_UL+wb], bl1 = sm[W_UL+wb+4];
                bmma(d0, Ah[0][s], bh0, bh1);
                bmma(d0, Ah[0][s], bl0, bl1);
                bmma(d0, Al[0][s], bh0, bh1);
                bmma(d1, Ah[1][s], bh0, bh1);
                bmma(d1, Ah[1][s], bl0, bl1);
                bmma(d1, Al[1][s], bh0, bh1);
            }
            size_t o0 = (size_t)(row0 + (wm*2+0)*16 + lr)*4096 + ch*128 + t*8 + lc*2;
            size_t o1 = (size_t)(row0 + (wm*2+1)*16 + lr)*4096 + ch*128 + t*8 + lc*2;
            *(float2*)&out[o0]          = make_float2(d0[0], d0[1]);
            *(float2*)&out[o0 + 8*4096] = make_float2(d0[2], d0[3]);
            *(float2*)&out[o1]          = make_float2(d1[0], d1[1]);
            *(float2*)&out[o1 + 8*4096] = make_float2(d1[2], d1[3]);
        }
    }
}

extern "C" void kernel_launch(void* const* d_in, const int* in_sizes, int n_in,
                              void* d_out, int out_size)
{
    const float*     x  = (const float*)d_in[0];      // [16384,4096]
    const float*     dw = (const float*)d_in[1];      // [64,4096]
    const float*     uw = (const float*)d_in[2];      // [4096,64]
    const float*     tv = (const float*)d_in[3];      // [16384,8]
    const long long* ti = (const long long*)d_in[4];  // [16384,8] i32/i64

    cudaFuncSetAttribute(moe_mma, cudaFuncAttributeMaxDynamicSharedMemorySize, SMEM_SZ);
    kprep<<<2048, 256>>>(dw, uw);
    moe_mma<<<NCTA, THR, SMEM_SZ>>>(x, tv, ti, (float*)d_out);
}

// round 11
// speedup vs baseline: 1.0978x; 1.0354x over previous
#include <cuda_runtime.h>
#include <cuda_bf16.h>
#include <cstdint>

#define NCTA 128
#define THR  512

// smem word offsets (4B words)
#define W_X0   0          // X f32 buf0: 128 rows x 72 words
#define W_X1   9216
#define W_DWH0 18432      // dw hi buf0: 64 x 36
#define W_DWH1 23040      //   (lo = hi + 2304)
#define W_UH0  0          // GEMM2 uw hi buf0: 128 x 36 (lo = +4608); reuses X region
#define W_UH1  9216
#define W_DSM  27648      // 128 x 66 f32
#define W_RH   36096      // 128 x 36 (bf16 in shorts, stride 72 shorts)
#define W_RL   40704
#define SMEM_SZ (45312*4)

__device__ unsigned short g_dwh[64*4096], g_dwl[64*4096];
__device__ unsigned short g_uwh[4096*64], g_uwl[4096*64];

static __device__ __forceinline__ uint32_t pk2(float lo, float hi) {
    uint32_t r; asm("cvt.rn.bf16x2.f32 %0, %1, %2;" : "=r"(r) : "f"(hi), "f"(lo)); return r;
}
static __device__ __forceinline__ void bmma(float d[4], const uint32_t a[4],
                                            uint32_t b0, uint32_t b1) {
    asm("mma.sync.aligned.m16n8k16.row.col.f32.bf16.bf16.f32 "
        "{%0,%1,%2,%3},{%4,%5,%6,%7},{%8,%9},{%0,%1,%2,%3};"
        : "+f"(d[0]), "+f"(d[1]), "+f"(d[2]), "+f"(d[3])
        : "r"(a[0]), "r"(a[1]), "r"(a[2]), "r"(a[3]), "r"(b0), "r"(b1));
}
static __device__ __forceinline__ uint32_t smem_u32(const void* p) {
    uint32_t a;
    asm("{ .reg .u64 t; cvta.to.shared.u64 t, %1; cvt.u32.u64 %0, t; }" : "=r"(a) : "l"(p));
    return a;
}
static __device__ __forceinline__ void cpa(uint32_t s, const void* g) {
    asm volatile("cp.async.ca.shared.global [%0], [%1], 16;" :: "r"(s), "l"(g) : "memory");
}
#define CPC()  asm volatile("cp.async.commit_group;" ::: "memory")
#define CPW1() asm volatile("cp.async.wait_group 1;" ::: "memory")
#define CPW0() asm volatile("cp.async.wait_group 0;" ::: "memory")

__global__ void kprep(const float* __restrict__ dw, const float* __restrict__ uw) {
    int i = blockIdx.x * 256 + threadIdx.x;
    float v = (i < 262144) ? dw[i] : uw[i - 262144];
    __nv_bfloat16 hb = __float2bfloat16(v);
    float l = v - __bfloat162float(hb);
    __nv_bfloat16 lb = __float2bfloat16(l);
    unsigned short hu = *(unsigned short*)&hb, lu = *(unsigned short*)&lb;
    if (i < 262144) { g_dwh[i] = hu; g_dwl[i] = lu; }
    else            { g_uwh[i - 262144] = hu; g_uwl[i - 262144] = lu; }
}

__global__ __launch_bounds__(THR, 1) void moe_mma(
    const float* __restrict__ x, const float* __restrict__ tv,
    const long long* __restrict__ ti, float* __restrict__ out)
{
    extern __shared__ uint32_t sm[];
    float* smf = (float*)sm;
    const uint32_t su = smem_u32(sm);
    const int tid = threadIdx.x, wid = tid >> 5, lane = tid & 31;
    const int lr = lane >> 2, lc = lane & 3;
    const int quarter = wid >> 2;                // k-quarter (GEMM1)
    const int team = wid & 3, tm = team >> 1, tn = team & 1;   // GEMM1 m64/n32 tile
    const int wm = wid >> 2, wn = wid & 3;       // GEMM2 mapping (as R10)
    const int row0 = blockIdx.x * 128;

    const float4* x4   = (const float4*)x;
    const uint4*  dwh4 = (const uint4*)g_dwh;
    const uint4*  dwl4 = (const uint4*)g_dwl;
    const uint4*  uwh4 = (const uint4*)g_uwh;
    const uint4*  uwl4 = (const uint4*)g_uwl;

    // ---- prologue: stage GEMM1 chunk 0 via cp.async ----
    {
        uint32_t xb = su + W_X0 * 4;
        #pragma unroll
        for (int j = 0; j < 4; j++) {
            int f = tid + j*THR, r = f >> 4, q = f & 15;
            cpa(xb + (r*72 + q*4)*4, x4 + (size_t)(row0 + r)*1024 + q);
        }
        uint32_t hb = su + W_DWH0 * 4;
        int n = tid >> 3, qw = tid & 7;
        cpa(hb + (n*36 + qw*4)*4,          dwh4 + n*512 + qw);
        cpa(hb + (2304 + n*36 + qw*4)*4,   dwl4 + n*512 + qw);
        CPC();
    }

    // ---- pack top-k indices (int32/int64 auto-detect, in-bounds) ----
    uint32_t plo = 0, phi = 0;
    {
        const int* t32b = (const int*)ti;
        bool is64 = ((t32b[1]|t32b[3]|t32b[5]|t32b[7]|t32b[9]|t32b[11]|t32b[13]|t32b[15]) == 0);
        if (tid < 128) {
            int row = row0 + tid;
            if (is64) {
                const long long* t = ti + (size_t)row * 8;
                #pragma unroll
                for (int k = 0; k < 4; k++) { plo |= ((uint32_t)t[k]&63u)<<(8*k); phi |= ((uint32_t)t[4+k]&63u)<<(8*k); }
            } else {
                const int* t = t32b + (size_t)row * 8;
                #pragma unroll
                for (int k = 0; k < 4; k++) { plo |= ((uint32_t)t[k]&63u)<<(8*k); phi |= ((uint32_t)t[4+k]&63u)<<(8*k); }
            }
        }
    }
    // zero R region (9216 words)
    #pragma unroll
    for (int j = 0; j < 18; j++) sm[W_RH + tid + j*THR] = 0;

    // ================== GEMM1: D1[128,64] = X_tile @ dw^T, split-K x4 ==================
    float acc[4][4][4];
    #pragma unroll
    for (int a = 0; a < 4; a++)
        #pragma unroll
        for (int b = 0; b < 4; b++) { acc[a][b][0]=acc[a][b][1]=acc[a][b][2]=acc[a][b][3]=0.f; }

    #pragma unroll 1
    for (int c = 0; c < 64; c++) {
        if (c < 63) {   // stage chunk c+1 into buf (c+1)&1
            uint32_t xb = su + (W_X0 + ((c+1)&1)*9216) * 4;
            #pragma unroll
            for (int j = 0; j < 4; j++) {
                int f = tid + j*THR, r = f >> 4, q = f & 15;
                cpa(xb + (r*72 + q*4)*4, x4 + (size_t)(row0 + r)*1024 + (c+1)*16 + q);
            }
            uint32_t hb = su + (W_DWH0 + ((c+1)&1)*4608) * 4;
            int n = tid >> 3, qw = tid & 7;
            cpa(hb + (n*36 + qw*4)*4,        dwh4 + n*512 + (c+1)*8 + qw);
            cpa(hb + (2304 + n*36 + qw*4)*4, dwl4 + n*512 + (c+1)*8 + qw);
            CPC();
            CPW1();
        } else {
            CPW0();
        }
        __syncthreads();

        if (quarter == (c & 3)) {
            const uint32_t xw = W_X0 + (c&1)*9216;
            const uint32_t bh = W_DWH0 + (c&1)*4608;
            const uint32_t bl = bh + 2304;
            #pragma unroll
            for (int s = 0; s < 4; s++) {
                uint32_t B0h[4], B1h[4], B0l[4], B1l[4];
                #pragma unroll
                for (int nt = 0; nt < 4; nt++) {
                    uint32_t wb = ((tn*4+nt)*8 + lr)*36 + s*8 + lc;
                    B0h[nt] = sm[bh+wb]; B1h[nt] = sm[bh+wb+4];
                    B0l[nt] = sm[bl+wb]; B1l[nt] = sm[bl+wb+4];
                }
                #pragma unroll
                for (int mp = 0; mp < 2; mp++) {
                    uint32_t ah[2][4], al[2][4];
                    #pragma unroll
                    for (int i = 0; i < 2; i++) {
                        int rowb = tm*64 + (mp*2+i)*16;
                        #pragma unroll
                        for (int j = 0; j < 4; j++) {
                            int r = rowb + lr + (j & 1)*8;
                            int ko = s*16 + lc*2 + (j >> 1)*8;
                            float2 f = *(float2*)&smf[xw + r*72 + ko];
                            uint32_t h = pk2(f.x, f.y);
                            float lx = f.x - __uint_as_float(h << 16);
                            float ly = f.y - __uint_as_float(h & 0xffff0000u);
                            ah[i][j] = h; al[i][j] = pk2(lx, ly);
                        }
                    }
                    #pragma unroll
                    for (int i = 0; i < 2; i++)
                        #pragma unroll
                        for (int nt = 0; nt < 4; nt++) bmma(acc[mp*2+i][nt], ah[i], B0h[nt], B1h[nt]);
                    #pragma unroll
                    for (int i = 0; i < 2; i++)
                        #pragma unroll
                        for (int nt = 0; nt < 4; nt++) bmma(acc[mp*2+i][nt], ah[i], B0l[nt], B1l[nt]);
                    #pragma unroll
                    for (int i = 0; i < 2; i++)
                        #pragma unroll
                        for (int nt = 0; nt < 4; nt++) bmma(acc[mp*2+i][nt], al[i], B0h[nt], B1h[nt]);
                }
            }
        }
        __syncthreads();
    }

    // ---- reduce 4 k-quarters into Dsm ----
    #pragma unroll 1
    for (int q = 0; q < 4; q++) {
        if (quarter == q) {
            #pragma unroll
            for (int mt = 0; mt < 4; mt++)
                #pragma unroll
                for (int nt = 0; nt < 4; nt++) {
                    uint32_t wd = W_DSM + (tm*64 + mt*16 + lr)*66 + tn*32 + nt*8 + lc*2;
                    if (q == 0) {
                        *(float2*)&sm[wd]       = make_float2(acc[mt][nt][0], acc[mt][nt][1]);
                        *(float2*)&sm[wd + 528] = make_float2(acc[mt][nt][2], acc[mt][nt][3]);
                    } else {
                        float2 u0 = *(float2*)&sm[wd], u1 = *(float2*)&sm[wd + 528];
                        u0.x += acc[mt][nt][0]; u0.y += acc[mt][nt][1];
                        u1.x += acc[mt][nt][2]; u1.y += acc[mt][nt][3];
                        *(float2*)&sm[wd]       = u0;
                        *(float2*)&sm[wd + 528] = u1;
                    }
                }
        }
        __syncthreads();
    }

    // ---- gather * scale -> sparse R (bf16 split) ----
    if (tid < 128) {
        const float* tvr = tv + (size_t)(row0 + tid)*8;
        #pragma unroll
        for (int k = 0; k < 8; k++) {
            uint32_t idx = ((k < 4 ? plo : phi) >> (8*(k&3))) & 63u;
            float v = smf[W_DSM + tid*66 + idx] * tvr[k];
            __nv_bfloat16 hb = __float2bfloat16(v);
            float l = v - __bfloat162float(hb);
            __nv_bfloat16 lb = __float2bfloat16(l);
            ((unsigned short*)&sm[W_RH])[tid*72 + idx] = *(unsigned short*)&hb;
            ((unsigned short*)&sm[W_RL])[tid*72 + idx] = *(unsigned short*)&lb;
        }
    }
    __syncthreads();

    // ---- R fragments register-resident (m32 per warp, R10 mapping) ----
    uint32_t Ah[2][4][4], Al[2][4][4];
    #pragma unroll
    for (int i = 0; i < 2; i++)
        #pragma unroll
        for (int s = 0; s < 4; s++) {
            uint32_t wa = ((wm*2+i)*16 + lr)*36 + s*8 + lc;
            Ah[i][s][0] = sm[W_RH+wa]; Ah[i][s][1] = sm[W_RH+wa+288]; Ah[i][s][2] = sm[W_RH+wa+4]; Ah[i][s][3] = sm[W_RH+wa+292];
            Al[i][s][0] = sm[W_RL+wa]; Al[i][s][1] = sm[W_RL+wa+288]; Al[i][s][2] = sm[W_RL+wa+4]; Al[i][s][3] = sm[W_RL+wa+292];
        }
    __syncthreads();   // everyone done reading R before U buffers overwrite region? (U region is W_X0.. — distinct from R) — keep for staging order

    // ---- prologue: stage GEMM2 chunk 0 ----
    {
        uint32_t ub = su + W_UH0 * 4;
        #pragma unroll
        for (int j = 0; j < 2; j++) {
            int f = tid + j*THR, n = f >> 3, qw = f & 7;
            cpa(ub + (n*36 + qw*4)*4,          uwh4 + n*8 + qw);
            cpa(ub + (4608 + n*36 + qw*4)*4,   uwl4 + n*8 + qw);
        }
        CPC();
    }

    // ========== GEMM2: out[128,4096] = R @ uw^T, 32 chunks of 128 cols ==========
    #pragma unroll 1
    for (int ch = 0; ch < 32; ch++) {
        if (ch < 31) {
            uint32_t ub = su + (W_UH0 + ((ch+1)&1)*9216) * 4;
            #pragma unroll
            for (int j = 0; j < 2; j++) {
                int f = tid + j*THR, n = f >> 3, qw = f & 7;
                cpa(ub + (n*36 + qw*4)*4,        uwh4 + (size_t)(ch+1)*1024 + n*8 + qw);
                cpa(ub + (4608 + n*36 + qw*4)*4, uwl4 + (size_t)(ch+1)*1024 + n*8 + qw);
            }
            CPC();
            CPW1();
        } else {
            CPW0();
        }
        __syncthreads();

        const uint32_t uh = W_UH0 + (ch&1)*9216;
        const uint32_t ul = uh + 4608;
        #pragma unroll
        for (int tt = 0; tt < 4; tt++) {
            int t = wn*4 + tt;
            float d0[4] = {0.f,0.f,0.f,0.f}, d1[4] = {0.f,0.f,0.f,0.f};
            #pragma unroll
            for (int s = 0; s < 4; s++) {
                uint32_t wb = (t*8 + lr)*36 + s*8 + lc;
                uint32_t bh0 = sm[uh+wb], bh1 = sm[uh+wb+4];
                uint32_t bl0 = sm[ul+wb], bl1 = sm[ul+wb+4];
                bmma(d0, Ah[0][s], bh0, bh1);
                bmma(d0, Ah[0][s], bl0, bl1);
                bmma(d0, Al[0][s], bh0, bh1);
                bmma(d1, Ah[1][s], bh0, bh1);
                bmma(d1, Ah[1][s], bl0, bl1);
                bmma(d1, Al[1][s], bh0, bh1);
            }
            size_t o0 = (size_t)(row0 + (wm*2+0)*16 + lr)*4096 + ch*128 + t*8 + lc*2;
            size_t o1 = (size_t)(row0 + (wm*2+1)*16 + lr)*4096 + ch*128 + t*8 + lc*2;
            *(float2*)&out[o0]          = make_float2(d0[0], d0[1]);
            *(float2*)&out[o0 + 8*4096] = make_float2(d0[2], d0[3]);
            *(float2*)&out[o1]          = make_float2(d1[0], d1[1]);
            *(float2*)&out[o1 + 8*4096] = make_float2(d1[2], d1[3]);
        }
        __syncthreads();
    }
}

extern "C" void kernel_launch(void* const* d_in, const int* in_sizes, int n_in,
                              void* d_out, int out_size)
{
    const float*     x  = (const float*)d_in[0];      // [16384,4096]
    const float*     dw = (const float*)d_in[1];      // [64,4096]
    const float*     uw = (const float*)d_in[2];      // [4096,64]
    const float*     tv = (const float*)d_in[3];      // [16384,8]
    const long long* ti = (const long long*)d_in[4];  // [16384,8] i32/i64

    cudaFuncSetAttribute(moe_mma, cudaFuncAttributeMaxDynamicSharedMemorySize, SMEM_SZ);
    kprep<<<2048, 256>>>(dw, uw);
    moe_mma<<<NCTA, THR, SMEM_SZ>>>(x, tv, ti, (float*)d_out);
}